// round 6
// baseline (speedup 1.0000x reference)
#include <cuda_runtime.h>
#include <cuda_bf16.h>
#include <cstdint>

// Problem constants (fixed shapes for this problem instance)
#define BB   4
#define TT   4096
#define HH   1024
#define WIN  256
#define SCALE 0.03125f   // 1/sqrt(1024)

// 64 MB scratch for K = h @ W^T
__device__ float g_K[(size_t)BB * TT * HH];

__device__ __forceinline__ float neg_inf() { return __int_as_float(0xff800000); }

// ---------------------------------------------------------------------------
// Kernel 1: K projection GEMM.  C[m][n] = sum_k A[m][k] * W[n][k]
// A = h flattened (M=16384 x K=1024), W (N=1024 x K=1024), C = g_K (M x N)
// 128x128x16 tiles, 256 threads, 8x8 per thread.
// ---------------------------------------------------------------------------
#define GM_BM 128
#define GM_BN 128
#define GM_BK 16
#define GM_LDA (GM_BM + 4)

__global__ __launch_bounds__(256) void kproj_gemm(const float* __restrict__ A,
                                                  const float* __restrict__ Wm) {
    __shared__ float As[GM_BK][GM_LDA];
    __shared__ float Bs[GM_BK][GM_LDA];

    const int bm = blockIdx.y * GM_BM;
    const int bn = blockIdx.x * GM_BN;
    const int tid = threadIdx.x;
    const int tr = tid >> 4;   // 0..15
    const int tc = tid & 15;   // 0..15

    float acc[8][8];
#pragma unroll
    for (int i = 0; i < 8; i++)
#pragma unroll
        for (int j = 0; j < 8; j++) acc[i][j] = 0.f;

    for (int k0 = 0; k0 < HH; k0 += GM_BK) {
#pragma unroll
        for (int i = 0; i < 2; i++) {
            int lin = tid + i * 256;           // 0..511
            int row = lin >> 2;                // 0..127
            int c4  = (lin & 3) * 4;           // 0,4,8,12
            float4 va = *(const float4*)&A[(size_t)(bm + row) * HH + k0 + c4];
            As[c4 + 0][row] = va.x; As[c4 + 1][row] = va.y;
            As[c4 + 2][row] = va.z; As[c4 + 3][row] = va.w;
            float4 vb = *(const float4*)&Wm[(size_t)(bn + row) * HH + k0 + c4];
            Bs[c4 + 0][row] = vb.x; Bs[c4 + 1][row] = vb.y;
            Bs[c4 + 2][row] = vb.z; Bs[c4 + 3][row] = vb.w;
        }
        __syncthreads();

#pragma unroll
        for (int k = 0; k < GM_BK; k++) {
            float4 a0 = *(const float4*)&As[k][tr * 8];
            float4 a1 = *(const float4*)&As[k][tr * 8 + 4];
            float4 b0 = *(const float4*)&Bs[k][tc * 8];
            float4 b1 = *(const float4*)&Bs[k][tc * 8 + 4];
            float a[8] = {a0.x, a0.y, a0.z, a0.w, a1.x, a1.y, a1.z, a1.w};
            float b[8] = {b0.x, b0.y, b0.z, b0.w, b1.x, b1.y, b1.z, b1.w};
#pragma unroll
            for (int i = 0; i < 8; i++)
#pragma unroll
                for (int j = 0; j < 8; j++) acc[i][j] = fmaf(a[i], b[j], acc[i][j]);
        }
        __syncthreads();
    }

#pragma unroll
    for (int i = 0; i < 8; i++) {
        size_t row = (size_t)(bm + tr * 8 + i);
        float* p = &g_K[row * HH + bn + tc * 8];
        float4 v0 = make_float4(acc[i][0], acc[i][1], acc[i][2], acc[i][3]);
        float4 v1 = make_float4(acc[i][4], acc[i][5], acc[i][6], acc[i][7]);
        *(float4*)(p)     = v0;
        *(float4*)(p + 4) = v1;
    }
}

// ---------------------------------------------------------------------------
// Kernel 2: banded attention.
// One block per (b, 64-query tile). Band = [q0-256, q0+63] = 5 key tiles of 64.
// Phase 1: S[64][320] (smem) = scaled masked Q K^T
// Phase 2: row softmax
// Phase 3: O = P V, written in 64-wide H chunks
// ---------------------------------------------------------------------------
#define BQ   64
#define KT   64
#define NKT  5
#define BAND 320
#define SSTR 324          // 320 + 4 pad (multiple of 4 for float4)
#define HC   32
#define CSTR 68           // 64 + 4 pad

#define ATTN_SMEM_FLOATS (BQ * SSTR + 2 * HC * CSTR)   // 20736 + 4352 = 25088
#define ATTN_SMEM_BYTES  (ATTN_SMEM_FLOATS * 4)        // 100352

extern __shared__ float sm_attn[];

__global__ __launch_bounds__(256) void attn_kernel(const float* __restrict__ hbuf,
                                                   float* __restrict__ out) {
    float* S  = sm_attn;                    // [BQ][SSTR]
    float* Qc = sm_attn + BQ * SSTR;        // [HC][CSTR]
    float* Kc = Qc + HC * CSTR;             // [HC][CSTR]
    float* Vc = sm_attn + BQ * SSTR;        // [KT][CSTR] (reuses Qc/Kc space)

    const int b  = blockIdx.y;
    const int q0 = blockIdx.x * BQ;
    const float* hb = hbuf + (size_t)b * TT * HH;
    const float* Kb = g_K + (size_t)b * TT * HH;

    const int tid = threadIdx.x;
    const int tr = tid >> 4;   // 0..15
    const int tc = tid & 15;   // 0..15

    // -------- Phase 1: scores --------
    for (int kt = 0; kt < NKT; kt++) {
        const int kstart = q0 - WIN + kt * KT;
        float acc[4][4];
#pragma unroll
        for (int i = 0; i < 4; i++)
#pragma unroll
            for (int j = 0; j < 4; j++) acc[i][j] = 0.f;

        for (int h0 = 0; h0 < HH; h0 += HC) {
            __syncthreads();
#pragma unroll
            for (int i = 0; i < 2; i++) {
                int lin = tid + i * 256;        // 0..511
                int row = lin >> 3;             // 0..63
                int c4  = (lin & 7) * 4;        // 0..28
                float4 v = *(const float4*)&hb[(size_t)(q0 + row) * HH + h0 + c4];
                Qc[(c4 + 0) * CSTR + row] = v.x;
                Qc[(c4 + 1) * CSTR + row] = v.y;
                Qc[(c4 + 2) * CSTR + row] = v.z;
                Qc[(c4 + 3) * CSTR + row] = v.w;
                int kr = kstart + row;
                float4 w = make_float4(0.f, 0.f, 0.f, 0.f);
                if (kr >= 0) w = *(const float4*)&Kb[(size_t)kr * HH + h0 + c4];
                Kc[(c4 + 0) * CSTR + row] = w.x;
                Kc[(c4 + 1) * CSTR + row] = w.y;
                Kc[(c4 + 2) * CSTR + row] = w.z;
                Kc[(c4 + 3) * CSTR + row] = w.w;
            }
            __syncthreads();

#pragma unroll
            for (int k = 0; k < HC; k++) {
                float4 av = *(const float4*)&Qc[k * CSTR + tr * 4];
                float4 bv = *(const float4*)&Kc[k * CSTR + tc * 4];
                float a[4] = {av.x, av.y, av.z, av.w};
                float bb[4] = {bv.x, bv.y, bv.z, bv.w};
#pragma unroll
                for (int i = 0; i < 4; i++)
#pragma unroll
                    for (int j = 0; j < 4; j++)
                        acc[i][j] = fmaf(a[i], bb[j], acc[i][j]);
            }
        }

        // write scaled + masked scores into S
#pragma unroll
        for (int i = 0; i < 4; i++) {
            int q = q0 + tr * 4 + i;
            float4 v;
            float* vv = (float*)&v;
#pragma unroll
            for (int j = 0; j < 4; j++) {
                int kc = kstart + tc * 4 + j;
                bool valid = (kc >= 0) && (kc <= q) && (kc >= q - (WIN - 1));
                vv[j] = valid ? acc[i][j] * SCALE : neg_inf();
            }
            *(float4*)&S[(tr * 4 + i) * SSTR + kt * KT + tc * 4] = v;
        }
    }
    __syncthreads();

    // -------- Phase 2: softmax (8 warps x 8 rows each) --------
    {
        const int warp = tid >> 5;
        const int lane = tid & 31;
        for (int r = warp; r < BQ; r += 8) {
            float* row = &S[r * SSTR];
            float m = neg_inf();
#pragma unroll
            for (int c = lane; c < BAND; c += 32) m = fmaxf(m, row[c]);
#pragma unroll
            for (int o = 16; o; o >>= 1) m = fmaxf(m, __shfl_xor_sync(0xffffffffu, m, o));
            float s = 0.f;
#pragma unroll
            for (int c = lane; c < BAND; c += 32) {
                float p = __expf(row[c] - m);
                row[c] = p;
                s += p;
            }
#pragma unroll
            for (int o = 16; o; o >>= 1) s += __shfl_xor_sync(0xffffffffu, s, o);
            float inv = 1.f / s;
#pragma unroll
            for (int c = lane; c < BAND; c += 32) row[c] *= inv;
        }
    }
    __syncthreads();

    // -------- Phase 3: context O = P V --------
    for (int h0 = 0; h0 < HH; h0 += 64) {
        float acc[4][4];
#pragma unroll
        for (int i = 0; i < 4; i++)
#pragma unroll
            for (int j = 0; j < 4; j++) acc[i][j] = 0.f;

        for (int kt = 0; kt < NKT; kt++) {
            const int kstart = q0 - WIN + kt * KT;
            __syncthreads();
#pragma unroll
            for (int i = 0; i < 4; i++) {
                int lin = tid + i * 256;       // 0..1023
                int row = lin >> 4;            // 0..63
                int c4  = (lin & 15) * 4;      // 0..60
                int kr = kstart + row;
                float4 v = make_float4(0.f, 0.f, 0.f, 0.f);
                if (kr >= 0) v = *(const float4*)&hb[(size_t)kr * HH + h0 + c4];
                *(float4*)&Vc[row * CSTR + c4] = v;
            }
            __syncthreads();

#pragma unroll
            for (int kk = 0; kk < KT; kk++) {
                float4 bv = *(const float4*)&Vc[kk * CSTR + tc * 4];
                float bb[4] = {bv.x, bv.y, bv.z, bv.w};
                float a0 = S[(tr * 4 + 0) * SSTR + kt * KT + kk];
                float a1 = S[(tr * 4 + 1) * SSTR + kt * KT + kk];
                float a2 = S[(tr * 4 + 2) * SSTR + kt * KT + kk];
                float a3 = S[(tr * 4 + 3) * SSTR + kt * KT + kk];
                float a[4] = {a0, a1, a2, a3};
#pragma unroll
                for (int i = 0; i < 4; i++)
#pragma unroll
                    for (int j = 0; j < 4; j++)
                        acc[i][j] = fmaf(a[i], bb[j], acc[i][j]);
            }
        }

#pragma unroll
        for (int i = 0; i < 4; i++) {
            size_t row = (size_t)b * TT + q0 + tr * 4 + i;
            *(float4*)&out[row * HH + h0 + tc * 4] =
                make_float4(acc[i][0], acc[i][1], acc[i][2], acc[i][3]);
        }
    }
}

// ---------------------------------------------------------------------------
// Launch
// ---------------------------------------------------------------------------
extern "C" void kernel_launch(void* const* d_in, const int* in_sizes, int n_in,
                              void* d_out, int out_size) {
    const float* h  = (const float*)d_in[0];
    const float* Wm = (const float*)d_in[1];
    // d_in[2] = T_hist (fixed at 256 for this problem shape)
    float* out = (float*)d_out;

    cudaFuncSetAttribute(attn_kernel, cudaFuncAttributeMaxDynamicSharedMemorySize,
                         ATTN_SMEM_BYTES);

    dim3 ggrid(HH / GM_BN, (BB * TT) / GM_BM);   // (8, 128)
    kproj_gemm<<<ggrid, 256>>>(h, Wm);

    dim3 agrid(TT / BQ, BB);                     // (64, 4)
    attn_kernel<<<agrid, 256, ATTN_SMEM_BYTES>>>(h, out);
}

// round 10
// speedup vs baseline: 1.3530x; 1.3530x over previous
#include <cuda_runtime.h>
#include <cuda_bf16.h>
#include <mma.h>
#include <cstdint>

using namespace nvcuda;

// Problem constants (fixed shapes for this problem instance)
#define BB   4
#define TT   4096
#define HH   1024
#define WIN  256
#define SCALE 0.03125f   // 1/sqrt(1024)
#define MTOT (BB*TT)     // 16384

// Scratch: K = h @ W^T (fp32), plus bf16 hi/lo splits of h and W
__device__ float g_K[(size_t)BB * TT * HH];
__device__ __nv_bfloat16 g_Ah[(size_t)MTOT * HH];
__device__ __nv_bfloat16 g_Al[(size_t)MTOT * HH];
__device__ __nv_bfloat16 g_Wh[(size_t)HH * HH];
__device__ __nv_bfloat16 g_Wl[(size_t)HH * HH];

__device__ __forceinline__ float neg_inf() { return __int_as_float(0xff800000); }

__device__ __forceinline__ uint32_t smem_u32(const void* p) {
    uint32_t a;
    asm("{ .reg .u64 t; cvta.to.shared.u64 t, %1; cvt.u32.u64 %0, t; }"
        : "=r"(a) : "l"(p));
    return a;
}

__device__ __forceinline__ void cp_async16(uint32_t saddr, const void* gaddr) {
    asm volatile("cp.async.cg.shared.global [%0], [%1], 16;\n"
                 :: "r"(saddr), "l"(gaddr));
}
__device__ __forceinline__ void cp_commit() {
    asm volatile("cp.async.commit_group;\n" ::: "memory");
}
template <int N>
__device__ __forceinline__ void cp_wait() {
    asm volatile("cp.async.wait_group %0;\n" :: "n"(N) : "memory");
}

// ---------------------------------------------------------------------------
// Split fp32 -> bf16 hi/lo.  WHICH=0: h -> g_Ah/g_Al ; WHICH=1: W -> g_Wh/g_Wl
// ---------------------------------------------------------------------------
template <int WHICH>
__global__ __launch_bounds__(256) void split_bf16_kernel(const float* __restrict__ x, int n4) {
    int i = blockIdx.x * blockDim.x + threadIdx.x;
    if (i >= n4) return;
    __nv_bfloat16* hi = WHICH ? g_Wh : g_Ah;
    __nv_bfloat16* lo = WHICH ? g_Wl : g_Al;
    float4 v = ((const float4*)x)[i];
    union { __nv_bfloat16 b[4]; uint2 u; } H, L;
    H.b[0] = __float2bfloat16(v.x);
    H.b[1] = __float2bfloat16(v.y);
    H.b[2] = __float2bfloat16(v.z);
    H.b[3] = __float2bfloat16(v.w);
    L.b[0] = __float2bfloat16(v.x - __bfloat162float(H.b[0]));
    L.b[1] = __float2bfloat16(v.y - __bfloat162float(H.b[1]));
    L.b[2] = __float2bfloat16(v.z - __bfloat162float(H.b[2]));
    L.b[3] = __float2bfloat16(v.w - __bfloat162float(H.b[3]));
    ((uint2*)hi)[i] = H.u;
    ((uint2*)lo)[i] = L.u;
}

// ---------------------------------------------------------------------------
// wmma bf16 split GEMM: g_K[m][n] = sum_k A[m][k]*W[n][k]
//   = Ah*Wh + Ah*Wl + Al*Wh  (fp32 accumulate)
// Block tile 128x128x32, 256 threads (8 warps, 4x2 warp grid, 32x64 per warp).
// cp.async double-buffered smem, ldm = 48 bf16 (96B, conflict-avoiding pad).
// ---------------------------------------------------------------------------
#define GBM 128
#define GBN 128
#define GBK 32
#define NIT (HH / GBK)          // 32
#define LDT 48                  // bf16 leading dim (padded from 32)
#define TILE_B (128 * LDT * 2)  // 12288 bytes per tile
#define STAGE_B (4 * TILE_B)    // Ah, Al, Wh, Wl = 49152
#define GEMM_DSMEM (2 * STAGE_B)  // 98304

extern __shared__ __align__(16) char g_dsm[];

__device__ __forceinline__ void load_stage(char* stage, int bm, int bn, int k0, int tid) {
    // 4 tiles x 512 16B-chunks; each thread does 2 chunks per tile.
#pragma unroll
    for (int half = 0; half < 2; ++half) {
        int c = tid + half * 256;       // 0..511
        int row = c >> 2;               // 0..127
        int c16 = c & 3;                // 16B unit within 32 bf16 = 64B row
        uint32_t soff = row * (LDT * 2) + c16 * 16;
        size_t aoff = (size_t)(bm + row) * HH + k0 + c16 * 8;
        size_t woff = (size_t)(bn + row) * HH + k0 + c16 * 8;
        cp_async16(smem_u32(stage + 0 * TILE_B + soff), g_Ah + aoff);
        cp_async16(smem_u32(stage + 1 * TILE_B + soff), g_Al + aoff);
        cp_async16(smem_u32(stage + 2 * TILE_B + soff), g_Wh + woff);
        cp_async16(smem_u32(stage + 3 * TILE_B + soff), g_Wl + woff);
    }
}

__global__ __launch_bounds__(256) void kproj_wmma() {
    const int tid = threadIdx.x;
    const int wid = tid >> 5;
    const int warp_m = wid & 3;         // 0..3 -> rows warp_m*32
    const int warp_n = wid >> 2;        // 0..1 -> cols warp_n*64

    const int bm = blockIdx.y * GBM;
    const int bn = blockIdx.x * GBN;

    wmma::fragment<wmma::accumulator, 16, 16, 16, float> acc[2][4];
#pragma unroll
    for (int i = 0; i < 2; i++)
#pragma unroll
        for (int j = 0; j < 4; j++) wmma::fill_fragment(acc[i][j], 0.f);

    // Prologue: stage 0
    load_stage(g_dsm, bm, bn, 0, tid);
    cp_commit();

    for (int c = 0; c < NIT; ++c) {
        if (c + 1 < NIT) {
            load_stage(g_dsm + ((c + 1) & 1) * STAGE_B, bm, bn, (c + 1) * GBK, tid);
            cp_commit();
            cp_wait<1>();
        } else {
            cp_wait<0>();
        }
        __syncthreads();

        const char* stage = g_dsm + (c & 1) * STAGE_B;
        const __nv_bfloat16* tAh = (const __nv_bfloat16*)(stage + 0 * TILE_B);
        const __nv_bfloat16* tAl = (const __nv_bfloat16*)(stage + 1 * TILE_B);
        const __nv_bfloat16* tWh = (const __nv_bfloat16*)(stage + 2 * TILE_B);
        const __nv_bfloat16* tWl = (const __nv_bfloat16*)(stage + 3 * TILE_B);

#pragma unroll
        for (int ks = 0; ks < GBK; ks += 16) {
            wmma::fragment<wmma::matrix_a, 16, 16, 16, __nv_bfloat16, wmma::row_major> ah[2], al[2];
            wmma::fragment<wmma::matrix_b, 16, 16, 16, __nv_bfloat16, wmma::col_major> wh[4], wl[4];
#pragma unroll
            for (int i = 0; i < 2; i++) {
                int r = warp_m * 32 + i * 16;
                wmma::load_matrix_sync(ah[i], tAh + r * LDT + ks, LDT);
                wmma::load_matrix_sync(al[i], tAl + r * LDT + ks, LDT);
            }
#pragma unroll
            for (int j = 0; j < 4; j++) {
                int n = warp_n * 64 + j * 16;
                wmma::load_matrix_sync(wh[j], tWh + n * LDT + ks, LDT);
                wmma::load_matrix_sync(wl[j], tWl + n * LDT + ks, LDT);
            }
#pragma unroll
            for (int i = 0; i < 2; i++)
#pragma unroll
                for (int j = 0; j < 4; j++) {
                    wmma::mma_sync(acc[i][j], ah[i], wh[j], acc[i][j]);
                    wmma::mma_sync(acc[i][j], ah[i], wl[j], acc[i][j]);
                    wmma::mma_sync(acc[i][j], al[i], wh[j], acc[i][j]);
                }
        }
        __syncthreads();
    }

    // Epilogue: store fp32 result
#pragma unroll
    for (int i = 0; i < 2; i++) {
        int r = bm + warp_m * 32 + i * 16;
#pragma unroll
        for (int j = 0; j < 4; j++) {
            int n = bn + warp_n * 64 + j * 16;
            wmma::store_matrix_sync(&g_K[(size_t)r * HH + n], acc[i][j], HH,
                                    wmma::mem_row_major);
        }
    }
}

// ---------------------------------------------------------------------------
// Kernel 2: banded attention (unchanged, known-good).
// ---------------------------------------------------------------------------
#define BQ   64
#define KT   64
#define NKT  5
#define BAND 320
#define SSTR 324
#define HC   32
#define CSTR 68

#define ATTN_SMEM_FLOATS (BQ * SSTR + 2 * HC * CSTR)
#define ATTN_SMEM_BYTES  (ATTN_SMEM_FLOATS * 4)

extern __shared__ float sm_attn[];

__global__ __launch_bounds__(256) void attn_kernel(const float* __restrict__ hbuf,
                                                   float* __restrict__ out) {
    float* S  = sm_attn;                    // [BQ][SSTR]
    float* Qc = sm_attn + BQ * SSTR;        // [HC][CSTR]
    float* Kc = Qc + HC * CSTR;             // [HC][CSTR]
    float* Vc = sm_attn + BQ * SSTR;        // [KT][CSTR] (reuses Qc/Kc space)

    const int b  = blockIdx.y;
    const int q0 = blockIdx.x * BQ;
    const float* hb = hbuf + (size_t)b * TT * HH;
    const float* Kb = g_K + (size_t)b * TT * HH;

    const int tid = threadIdx.x;
    const int tr = tid >> 4;
    const int tc = tid & 15;

    // -------- Phase 1: scores --------
    for (int kt = 0; kt < NKT; kt++) {
        const int kstart = q0 - WIN + kt * KT;
        float acc[4][4];
#pragma unroll
        for (int i = 0; i < 4; i++)
#pragma unroll
            for (int j = 0; j < 4; j++) acc[i][j] = 0.f;

        for (int h0 = 0; h0 < HH; h0 += HC) {
            __syncthreads();
#pragma unroll
            for (int i = 0; i < 2; i++) {
                int lin = tid + i * 256;
                int row = lin >> 3;
                int c4  = (lin & 7) * 4;
                float4 v = *(const float4*)&hb[(size_t)(q0 + row) * HH + h0 + c4];
                Qc[(c4 + 0) * CSTR + row] = v.x;
                Qc[(c4 + 1) * CSTR + row] = v.y;
                Qc[(c4 + 2) * CSTR + row] = v.z;
                Qc[(c4 + 3) * CSTR + row] = v.w;
                int kr = kstart + row;
                float4 w = make_float4(0.f, 0.f, 0.f, 0.f);
                if (kr >= 0) w = *(const float4*)&Kb[(size_t)kr * HH + h0 + c4];
                Kc[(c4 + 0) * CSTR + row] = w.x;
                Kc[(c4 + 1) * CSTR + row] = w.y;
                Kc[(c4 + 2) * CSTR + row] = w.z;
                Kc[(c4 + 3) * CSTR + row] = w.w;
            }
            __syncthreads();

#pragma unroll
            for (int k = 0; k < HC; k++) {
                float4 av = *(const float4*)&Qc[k * CSTR + tr * 4];
                float4 bv = *(const float4*)&Kc[k * CSTR + tc * 4];
                float a[4] = {av.x, av.y, av.z, av.w};
                float bb[4] = {bv.x, bv.y, bv.z, bv.w};
#pragma unroll
                for (int i = 0; i < 4; i++)
#pragma unroll
                    for (int j = 0; j < 4; j++)
                        acc[i][j] = fmaf(a[i], bb[j], acc[i][j]);
            }
        }

#pragma unroll
        for (int i = 0; i < 4; i++) {
            int q = q0 + tr * 4 + i;
            float4 v;
            float* vv = (float*)&v;
#pragma unroll
            for (int j = 0; j < 4; j++) {
                int kc = kstart + tc * 4 + j;
                bool valid = (kc >= 0) && (kc <= q) && (kc >= q - (WIN - 1));
                vv[j] = valid ? acc[i][j] * SCALE : neg_inf();
            }
            *(float4*)&S[(tr * 4 + i) * SSTR + kt * KT + tc * 4] = v;
        }
    }
    __syncthreads();

    // -------- Phase 2: softmax --------
    {
        const int warp = tid >> 5;
        const int lane = tid & 31;
        for (int r = warp; r < BQ; r += 8) {
            float* row = &S[r * SSTR];
            float m = neg_inf();
#pragma unroll
            for (int c = lane; c < BAND; c += 32) m = fmaxf(m, row[c]);
#pragma unroll
            for (int o = 16; o; o >>= 1) m = fmaxf(m, __shfl_xor_sync(0xffffffffu, m, o));
            float s = 0.f;
#pragma unroll
            for (int c = lane; c < BAND; c += 32) {
                float p = __expf(row[c] - m);
                row[c] = p;
                s += p;
            }
#pragma unroll
            for (int o = 16; o; o >>= 1) s += __shfl_xor_sync(0xffffffffu, s, o);
            float inv = 1.f / s;
#pragma unroll
            for (int c = lane; c < BAND; c += 32) row[c] *= inv;
        }
    }
    __syncthreads();

    // -------- Phase 3: context O = P V --------
    for (int h0 = 0; h0 < HH; h0 += 64) {
        float acc[4][4];
#pragma unroll
        for (int i = 0; i < 4; i++)
#pragma unroll
            for (int j = 0; j < 4; j++) acc[i][j] = 0.f;

        for (int kt = 0; kt < NKT; kt++) {
            const int kstart = q0 - WIN + kt * KT;
            __syncthreads();
#pragma unroll
            for (int i = 0; i < 4; i++) {
                int lin = tid + i * 256;
                int row = lin >> 4;
                int c4  = (lin & 15) * 4;
                int kr = kstart + row;
                float4 v = make_float4(0.f, 0.f, 0.f, 0.f);
                if (kr >= 0) v = *(const float4*)&hb[(size_t)kr * HH + h0 + c4];
                *(float4*)&Vc[row * CSTR + c4] = v;
            }
            __syncthreads();

#pragma unroll
            for (int kk = 0; kk < KT; kk++) {
                float4 bv = *(const float4*)&Vc[kk * CSTR + tc * 4];
                float bb[4] = {bv.x, bv.y, bv.z, bv.w};
                float a0 = S[(tr * 4 + 0) * SSTR + kt * KT + kk];
                float a1 = S[(tr * 4 + 1) * SSTR + kt * KT + kk];
                float a2 = S[(tr * 4 + 2) * SSTR + kt * KT + kk];
                float a3 = S[(tr * 4 + 3) * SSTR + kt * KT + kk];
                float a[4] = {a0, a1, a2, a3};
#pragma unroll
                for (int i = 0; i < 4; i++)
#pragma unroll
                    for (int j = 0; j < 4; j++)
                        acc[i][j] = fmaf(a[i], bb[j], acc[i][j]);
            }
        }

#pragma unroll
        for (int i = 0; i < 4; i++) {
            size_t row = (size_t)b * TT + q0 + tr * 4 + i;
            *(float4*)&out[row * HH + h0 + tc * 4] =
                make_float4(acc[i][0], acc[i][1], acc[i][2], acc[i][3]);
        }
    }
}

// ---------------------------------------------------------------------------
// Launch
// ---------------------------------------------------------------------------
extern "C" void kernel_launch(void* const* d_in, const int* in_sizes, int n_in,
                              void* d_out, int out_size) {
    const float* h  = (const float*)d_in[0];
    const float* Wm = (const float*)d_in[1];
    float* out = (float*)d_out;

    cudaFuncSetAttribute(kproj_wmma, cudaFuncAttributeMaxDynamicSharedMemorySize,
                         GEMM_DSMEM);
    cudaFuncSetAttribute(attn_kernel, cudaFuncAttributeMaxDynamicSharedMemorySize,
                         ATTN_SMEM_BYTES);

    // Split fp32 -> bf16 hi/lo
    int n4h = (MTOT * HH) / 4;     // 4194304
    int n4w = (HH * HH) / 4;       // 262144
    split_bf16_kernel<0><<<n4h / 256, 256>>>(h, n4h);
    split_bf16_kernel<1><<<n4w / 256, 256>>>(Wm, n4w);

    // K projection via wmma (HMMA tensor path — tcgen05 unavailable at sm_103 PTX target)
    dim3 ggrid(HH / GBN, MTOT / GBM);   // (8, 128)
    kproj_wmma<<<ggrid, 256, GEMM_DSMEM>>>();

    // Banded attention
    dim3 agrid(TT / BQ, BB);            // (64, 4)
    attn_kernel<<<agrid, 256, ATTN_SMEM_BYTES>>>(h, out);
}